// round 15
// baseline (speedup 1.0000x reference)
#include <cuda_runtime.h>
#include <cuda_bf16.h>
#include <cstdint>

#define BSZ   8
#define NNODE 20000
#define FIN   256
#define NH    8
#define ND    64
#define EDG   160000
#define NJ    16

__device__ __align__(16) float g_w[BSZ * NJ * FIN];         // effective weights (f32)
__device__ __align__(16) float g_scores[BSZ * NNODE * NJ];  // per-node scores

__device__ __forceinline__ void pdl_wait() {
    asm volatile("griddepcontrol.wait;" ::: "memory");
}
__device__ __forceinline__ void pdl_trigger() {
    asm volatile("griddepcontrol.launch_dependents;");
}

// ---------------------------------------------------------------------------
// Kernel 1: fold scoring vectors into projection weights.
//   g_w[b][j][f] = sum_d W[(h*64+d)*256+f] * s[b][h][d]
// ---------------------------------------------------------------------------
__global__ void build_w_kernel(const float* __restrict__ W,
                               const float* __restrict__ ssrc,
                               const float* __restrict__ strg) {
    pdl_trigger();   // let score_mma launch & run its x-prefetch concurrently
    __shared__ float4 part[4][64];
    const int tid = threadIdx.x;
    const int f4  = tid & 63;
    const int dg  = tid >> 6;
    const int bj  = blockIdx.x;      // 0..127
    const int b   = bj >> 4;
    const int j   = bj & 15;
    const int h   = j & 7;
    const float* __restrict__ s = (j < 8 ? ssrc : strg) + (b * NH + h) * ND;
    const float4* __restrict__ W4 = (const float4*)W;

    float4 acc = make_float4(0.f, 0.f, 0.f, 0.f);
#pragma unroll
    for (int k = 0; k < 16; ++k) {
        const int d = dg * 16 + k;
        const float4 w = W4[(h * ND + d) * 64 + f4];
        const float sv = __ldg(&s[d]);
        acc.x += w.x * sv; acc.y += w.y * sv; acc.z += w.z * sv; acc.w += w.w * sv;
    }
    part[dg][f4] = acc;
    __syncthreads();
    if (tid < 64) {
        float4 a = part[0][tid], b2 = part[1][tid], c = part[2][tid], d2 = part[3][tid];
        float4 r;
        r.x = (a.x + b2.x) + (c.x + d2.x);
        r.y = (a.y + b2.y) + (c.y + d2.y);
        r.z = (a.z + b2.z) + (c.z + d2.z);
        r.w = (a.w + b2.w) + (c.w + d2.w);
        ((float4*)g_w)[bj * 64 + tid] = r;
    }
}

// ---------------------------------------------------------------------------
// Kernel 2: scoring via warp-level mma.sync (bf16 hi/lo split, fp32 accum).
//   One warp per 16-row M-block; K=256 (16 chunks of k16); N=16 (2 n-tiles).
//   score = Ahi*Bhi + Ahi*Blo + Alo*Bhi   (lo*lo dropped, ~2^-32 rel)
//   K-permuted fragments: thread c owns logical k in {4c..4c+3} -> LDG.128 A.
//   PDL: x chunk-0 prefetched BEFORE griddepcontrol.wait (x independent of g_w).
// ---------------------------------------------------------------------------
__device__ __forceinline__ void split2(float f0, float f1,
                                       uint32_t& hi, float& r0, float& r1) {
    asm("cvt.rn.bf16x2.f32 %0, %1, %2;" : "=r"(hi) : "f"(f1), "f"(f0));
    r0 = f0 - __uint_as_float(hi << 16);
    r1 = f1 - __uint_as_float(hi & 0xFFFF0000u);
}
__device__ __forceinline__ uint32_t pack2(float f0, float f1) {
    uint32_t p;
    asm("cvt.rn.bf16x2.f32 %0, %1, %2;" : "=r"(p) : "f"(f1), "f"(f0));
    return p;
}
__device__ __forceinline__ void mma16816(float* c, const uint32_t* a,
                                         uint32_t b0, uint32_t b1) {
    asm volatile(
        "mma.sync.aligned.m16n8k16.row.col.f32.bf16.bf16.f32 "
        "{%0,%1,%2,%3}, {%4,%5,%6,%7}, {%8,%9}, {%0,%1,%2,%3};"
        : "+f"(c[0]), "+f"(c[1]), "+f"(c[2]), "+f"(c[3])
        : "r"(a[0]), "r"(a[1]), "r"(a[2]), "r"(a[3]), "r"(b0), "r"(b1));
}

#define WSTRIDE 264   // bf16 elements per weight row in smem (pad -> conflict-free)

__global__ __launch_bounds__(256)
void score_mma_kernel(const float* __restrict__ x) {
    __shared__ __align__(16) __nv_bfloat16 smw[2][NJ][WSTRIDE];

    const int tid  = threadIdx.x;
    const int warp = tid >> 5;
    const int lane = tid & 31;
    const int b    = blockIdx.y;
    const int row0 = blockIdx.x * 128 + warp * 16;
    const bool act = row0 < NNODE;

    const float* __restrict__ xb = x + (size_t)b * NNODE * FIN;
    const int rA = row0 + (lane >> 2);
    const int rB = rA + 8;
    const int c4 = (lane & 3) * 4;           // logical k base in chunk
    const int kc = (lane & 3) * 2;           // physical B slot offset
    const int nB = lane >> 2;

    const float* __restrict__ pA = xb + (size_t)rA * FIN + c4;
    const float* __restrict__ pB = xb + (size_t)rB * FIN + c4;

    // ---- prefetch chunk 0 BEFORE waiting on build_w (x is independent) ----
    float4 nfa, nfb;
    if (act) {
        nfa = __ldcs((const float4*)pA);
        nfb = __ldcs((const float4*)pB);
    }
    pdl_wait();   // g_w now valid

    // ---- build B (hi/lo bf16, k-permuted): 1024 float4s over 256 threads ----
    {
        const float4* __restrict__ w4 = (const float4*)(g_w + b * NJ * FIN);
#pragma unroll
        for (int i = 0; i < 4; ++i) {
            const int lin = i * 256 + tid;   // 0..1023
            const int n   = lin >> 6;        // 0..15
            const int k4  = lin & 63;
            const int ch  = k4 >> 2;
            const int c   = k4 & 3;
            const int k0  = ch * 16;
            const float4 v = w4[n * 64 + k4];
            uint32_t h01, h23;
            float r0, r1, r2, r3;
            split2(v.x, v.y, h01, r0, r1);
            split2(v.z, v.w, h23, r2, r3);
            const uint32_t l01 = pack2(r0, r1);
            const uint32_t l23 = pack2(r2, r3);
            *(uint32_t*)&smw[0][n][k0 + 2 * c]     = h01;
            *(uint32_t*)&smw[0][n][k0 + 8 + 2 * c] = h23;
            *(uint32_t*)&smw[1][n][k0 + 2 * c]     = l01;
            *(uint32_t*)&smw[1][n][k0 + 8 + 2 * c] = l23;
        }
    }
    __syncthreads();
    if (!act) return;

    float acc0[4] = {0.f, 0.f, 0.f, 0.f};
    float acc1[4] = {0.f, 0.f, 0.f, 0.f};

#pragma unroll
    for (int ch = 0; ch < 16; ++ch) {
        const int k0 = ch * 16;
        const float4 fa = nfa;
        const float4 fb = nfb;
        if (ch < 15) {   // prefetch next chunk (compile-time pipeline)
            nfa = __ldcs((const float4*)(pA + (ch + 1) * 16));
            nfb = __ldcs((const float4*)(pB + (ch + 1) * 16));
        }

        uint32_t ah[4], al[4];
        {
            float r0, r1;
            split2(fa.x, fa.y, ah[0], r0, r1); al[0] = pack2(r0, r1);
            split2(fb.x, fb.y, ah[1], r0, r1); al[1] = pack2(r0, r1);
            split2(fa.z, fa.w, ah[2], r0, r1); al[2] = pack2(r0, r1);
            split2(fb.z, fb.w, ah[3], r0, r1); al[3] = pack2(r0, r1);
        }

        const uint32_t bh00 = *(const uint32_t*)&smw[0][nB][k0 + kc];
        const uint32_t bh01 = *(const uint32_t*)&smw[0][nB][k0 + 8 + kc];
        const uint32_t bh10 = *(const uint32_t*)&smw[0][8 + nB][k0 + kc];
        const uint32_t bh11 = *(const uint32_t*)&smw[0][8 + nB][k0 + 8 + kc];
        const uint32_t bl00 = *(const uint32_t*)&smw[1][nB][k0 + kc];
        const uint32_t bl01 = *(const uint32_t*)&smw[1][nB][k0 + 8 + kc];
        const uint32_t bl10 = *(const uint32_t*)&smw[1][8 + nB][k0 + kc];
        const uint32_t bl11 = *(const uint32_t*)&smw[1][8 + nB][k0 + 8 + kc];

        mma16816(acc0, ah, bh00, bh01);
        mma16816(acc1, ah, bh10, bh11);
        mma16816(acc0, ah, bl00, bl01);
        mma16816(acc1, ah, bl10, bl11);
        mma16816(acc0, al, bh00, bh01);
        mma16816(acc1, al, bh10, bh11);
    }

    pdl_trigger();   // gather may launch; its index loads overlap our epilogue

    float* __restrict__ gs = g_scores + ((size_t)b * NNODE) * NJ;
    const int crow0 = row0 + (lane >> 2);
    const int crow1 = crow0 + 8;
    const int ccol  = (lane & 3) * 2;
    *(float2*)&gs[(size_t)crow0 * NJ + ccol]     = make_float2(acc0[0], acc0[1]);
    *(float2*)&gs[(size_t)crow1 * NJ + ccol]     = make_float2(acc0[2], acc0[3]);
    *(float2*)&gs[(size_t)crow0 * NJ + 8 + ccol] = make_float2(acc1[0], acc1[1]);
    *(float2*)&gs[(size_t)crow1 * NJ + 8 + ccol] = make_float2(acc1[2], acc1[3]);
}

// ---------------------------------------------------------------------------
// Kernel 3: edge gather + sigmoid, 4 edges per thread.
//   PDL: index loads issued before griddepcontrol.wait (independent of scores).
// ---------------------------------------------------------------------------
__device__ __forceinline__ float edge_score(int hidx, int tidx) {
    const float s = g_scores[(size_t)(hidx >> 3) * NJ + (hidx & 7)] +
                    g_scores[(size_t)(tidx >> 3) * NJ + 8 + (tidx & 7)];
    return 1.0f / (1.0f + __expf(-s));
}

__global__ void gather_kernel(const int4* __restrict__ head4,
                              const int4* __restrict__ tail4,
                              float4* __restrict__ out4, int total4) {
    const int i = blockIdx.x * blockDim.x + threadIdx.x;
    if (i >= total4) { pdl_wait(); return; }
    const int4 h = head4[i];
    const int4 t = tail4[i];
    pdl_wait();   // scores now valid
    float4 o;
    o.x = edge_score(h.x, t.x);
    o.y = edge_score(h.y, t.y);
    o.z = edge_score(h.z, t.z);
    o.w = edge_score(h.w, t.w);
    out4[i] = o;
}

// ---------------------------------------------------------------------------
extern "C" void kernel_launch(void* const* d_in, const int* in_sizes, int n_in,
                              void* d_out, int out_size) {
    const float* x    = nullptr;
    const float* W    = nullptr;
    const int*   head = nullptr;
    const int*   tail = nullptr;
    const float* ssrc = nullptr;
    const float* strg = nullptr;
    for (int i = 0; i < n_in; ++i) {
        const int sz = in_sizes[i];
        if (sz == BSZ * NNODE * FIN) {
            x = (const float*)d_in[i];
        } else if (sz == NH * ND * FIN) {
            W = (const float*)d_in[i];
        } else if (sz == BSZ * EDG) {
            if (!head) head = (const int*)d_in[i];
            else       tail = (const int*)d_in[i];
        } else if (sz == BSZ * NH * ND) {
            if (!ssrc) ssrc = (const float*)d_in[i];
            else       strg = (const float*)d_in[i];
        }
    }
    float* out = (float*)d_out;

    build_w_kernel<<<BSZ * NJ, 256>>>(W, ssrc, strg);

    // score with PDL (fallback: plain launch)
    {
        cudaLaunchConfig_t cfg = {};
        cfg.gridDim  = dim3(157, BSZ);
        cfg.blockDim = dim3(256);
        cfg.dynamicSmemBytes = 0;
        cfg.stream = 0;
        cudaLaunchAttribute at[1];
        at[0].id = cudaLaunchAttributeProgrammaticStreamSerialization;
        at[0].val.programmaticStreamSerializationAllowed = 1;
        cfg.attrs = at;
        cfg.numAttrs = 1;
        if (cudaLaunchKernelEx(&cfg, score_mma_kernel, x) != cudaSuccess) {
            dim3 g2(157, BSZ);
            score_mma_kernel<<<g2, 256>>>(x);
        }
    }

    // gather with PDL (fallback: plain launch)
    {
        const int total4 = BSZ * EDG / 4;
        const int nblk = (total4 + 255) / 256;
        cudaLaunchConfig_t cfg = {};
        cfg.gridDim  = dim3(nblk);
        cfg.blockDim = dim3(256);
        cfg.dynamicSmemBytes = 0;
        cfg.stream = 0;
        cudaLaunchAttribute at[1];
        at[0].id = cudaLaunchAttributeProgrammaticStreamSerialization;
        at[0].val.programmaticStreamSerializationAllowed = 1;
        cfg.attrs = at;
        cfg.numAttrs = 1;
        if (cudaLaunchKernelEx(&cfg, gather_kernel,
                               (const int4*)head, (const int4*)tail,
                               (float4*)out, total4) != cudaSuccess) {
            gather_kernel<<<nblk, 256>>>((const int4*)head, (const int4*)tail,
                                         (float4*)out, total4);
        }
    }
}

// round 16
// speedup vs baseline: 1.2037x; 1.2037x over previous
#include <cuda_runtime.h>
#include <cuda_bf16.h>
#include <cstdint>

#define BSZ   8
#define NNODE 20000
#define FIN   256
#define NH    8
#define ND    64
#define EDG   160000
#define NJ    16
#define TPB   157                       // tiles (128 rows) per batch
#define NBLK  (BSZ * TPB)               // 1256 score blocks

__device__ __align__(16) float g_w[BSZ * NJ * FIN];         // effective weights (f32)
__device__ __align__(16) float g_scores[BSZ * NNODE * NJ];  // per-node scores
__device__ int g_wdone = 0;                                 // builder completion count
__device__ int g_wflag = 0;                                 // all-built flag

// ---------------------------------------------------------------------------
// helpers: bf16 hi/lo split + warp mma
// ---------------------------------------------------------------------------
__device__ __forceinline__ void split2(float f0, float f1,
                                       uint32_t& hi, float& r0, float& r1) {
    asm("cvt.rn.bf16x2.f32 %0, %1, %2;" : "=r"(hi) : "f"(f1), "f"(f0));
    r0 = f0 - __uint_as_float(hi << 16);
    r1 = f1 - __uint_as_float(hi & 0xFFFF0000u);
}
__device__ __forceinline__ uint32_t pack2(float f0, float f1) {
    uint32_t p;
    asm("cvt.rn.bf16x2.f32 %0, %1, %2;" : "=r"(p) : "f"(f1), "f"(f0));
    return p;
}
__device__ __forceinline__ void mma16816(float* c, const uint32_t* a,
                                         uint32_t b0, uint32_t b1) {
    asm volatile(
        "mma.sync.aligned.m16n8k16.row.col.f32.bf16.bf16.f32 "
        "{%0,%1,%2,%3}, {%4,%5,%6,%7}, {%8,%9}, {%0,%1,%2,%3};"
        : "+f"(c[0]), "+f"(c[1]), "+f"(c[2]), "+f"(c[3])
        : "r"(a[0]), "r"(a[1]), "r"(a[2]), "r"(a[3]), "r"(b0), "r"(b1));
}

#define WSTRIDE 264   // bf16 elements per weight row in smem (pad -> conflict-free)

// ---------------------------------------------------------------------------
// Score kernel with FUSED weight build.
//   1-D grid of 1256 blocks: b = bid/157, tile = bid%157.
//   Blocks 0..127 first compute g_w row (bj = bid) -> fence -> count;
//   the 128th completer sets g_wflag.  Everyone prefetches x chunk 0,
//   then spins on g_wflag (builders are bids 0..127 => wave-1 resident,
//   spinners only ever wait on lower bids => no deadlock).
//   Then: k-permuted bf16 hi/lo split mma.sync mainloop (R14-proven).
// ---------------------------------------------------------------------------
__global__ __launch_bounds__(256)
void score_mma_kernel(const float* __restrict__ x,
                      const float* __restrict__ W,
                      const float* __restrict__ ssrc,
                      const float* __restrict__ strg) {
    __shared__ __align__(16) __nv_bfloat16 smw[2][NJ][WSTRIDE];
    __shared__ float4 part[4][64];

    const int tid  = threadIdx.x;
    const int warp = tid >> 5;
    const int lane = tid & 31;
    const int bid  = blockIdx.x;
    const int b    = bid / TPB;
    const int tile = bid - b * TPB;
    const int row0 = tile * 128 + warp * 16;
    const bool act = row0 < NNODE;

    // ---- A-side pointers + chunk-0 prefetch (independent of g_w) ----
    const float* __restrict__ xb = x + (size_t)b * NNODE * FIN;
    const int rA = row0 + (lane >> 2);
    const int rB = rA + 8;
    const int c4 = (lane & 3) * 4;           // logical k base in chunk
    const int kc = (lane & 3) * 2;           // physical B slot offset
    const int nB = lane >> 2;
    const float* __restrict__ pA = xb + (size_t)rA * FIN + c4;
    const float* __restrict__ pB = xb + (size_t)rB * FIN + c4;

    float4 nfa, nfb;
    if (act) {
        nfa = __ldcs((const float4*)pA);
        nfb = __ldcs((const float4*)pB);
    }

    // ---- builder stage: blocks 0..127 each produce one g_w row ----
    if (bid < BSZ * NJ) {
        const int bj = bid;
        const int bb = bj >> 4;
        const int j  = bj & 15;
        const int h  = j & 7;
        const int f4i = tid & 63;
        const int dg  = tid >> 6;
        const float* __restrict__ s =
            (j < 8 ? ssrc : strg) + (bb * NH + h) * ND;
        const float4* __restrict__ W4 = (const float4*)W;
        float4 acc = make_float4(0.f, 0.f, 0.f, 0.f);
#pragma unroll
        for (int k = 0; k < 16; ++k) {
            const int d = dg * 16 + k;
            const float4 w = W4[(h * ND + d) * 64 + f4i];
            const float sv = __ldg(&s[d]);
            acc.x += w.x * sv; acc.y += w.y * sv;
            acc.z += w.z * sv; acc.w += w.w * sv;
        }
        part[dg][f4i] = acc;
        __syncthreads();
        if (tid < 64) {
            float4 a0 = part[0][tid], a1 = part[1][tid],
                   a2 = part[2][tid], a3 = part[3][tid];
            float4 r;
            r.x = (a0.x + a1.x) + (a2.x + a3.x);
            r.y = (a0.y + a1.y) + (a2.y + a3.y);
            r.z = (a0.z + a1.z) + (a2.z + a3.z);
            r.w = (a0.w + a1.w) + (a2.w + a3.w);
            ((float4*)g_w)[bj * 64 + tid] = r;
        }
        __threadfence();
        __syncthreads();
        if (tid == 0) {
            if (atomicAdd(&g_wdone, 1) == BSZ * NJ - 1)
                atomicExch(&g_wflag, 1);
        }
    }

    // ---- wait for all weights (spin only on lower-bid producers) ----
    if (tid == 0) {
        while (*(volatile int*)&g_wflag == 0) { }
    }
    __syncthreads();
    __threadfence();   // acquire g_w stores

    // ---- build B (hi/lo bf16, k-permuted): 1024 float4s over 256 threads ----
    {
        const float4* __restrict__ w4 = (const float4*)(g_w + b * NJ * FIN);
#pragma unroll
        for (int i = 0; i < 4; ++i) {
            const int lin = i * 256 + tid;   // 0..1023
            const int n   = lin >> 6;        // 0..15
            const int k4  = lin & 63;
            const int ch  = k4 >> 2;
            const int c   = k4 & 3;
            const int k0  = ch * 16;
            const float4 v = w4[n * 64 + k4];
            uint32_t h01, h23;
            float r0, r1, r2, r3;
            split2(v.x, v.y, h01, r0, r1);
            split2(v.z, v.w, h23, r2, r3);
            const uint32_t l01 = pack2(r0, r1);
            const uint32_t l23 = pack2(r2, r3);
            *(uint32_t*)&smw[0][n][k0 + 2 * c]     = h01;
            *(uint32_t*)&smw[0][n][k0 + 8 + 2 * c] = h23;
            *(uint32_t*)&smw[1][n][k0 + 2 * c]     = l01;
            *(uint32_t*)&smw[1][n][k0 + 8 + 2 * c] = l23;
        }
    }
    __syncthreads();
    if (!act) return;

    float acc0[4] = {0.f, 0.f, 0.f, 0.f};
    float acc1[4] = {0.f, 0.f, 0.f, 0.f};

#pragma unroll
    for (int ch = 0; ch < 16; ++ch) {
        const int k0 = ch * 16;
        const float4 fa = nfa;
        const float4 fb = nfb;
        if (ch < 15) {
            nfa = __ldcs((const float4*)(pA + (ch + 1) * 16));
            nfb = __ldcs((const float4*)(pB + (ch + 1) * 16));
        }

        uint32_t ah[4], al[4];
        {
            float r0, r1;
            split2(fa.x, fa.y, ah[0], r0, r1); al[0] = pack2(r0, r1);
            split2(fb.x, fb.y, ah[1], r0, r1); al[1] = pack2(r0, r1);
            split2(fa.z, fa.w, ah[2], r0, r1); al[2] = pack2(r0, r1);
            split2(fb.z, fb.w, ah[3], r0, r1); al[3] = pack2(r0, r1);
        }

        const uint32_t bh00 = *(const uint32_t*)&smw[0][nB][k0 + kc];
        const uint32_t bh01 = *(const uint32_t*)&smw[0][nB][k0 + 8 + kc];
        const uint32_t bh10 = *(const uint32_t*)&smw[0][8 + nB][k0 + kc];
        const uint32_t bh11 = *(const uint32_t*)&smw[0][8 + nB][k0 + 8 + kc];
        const uint32_t bl00 = *(const uint32_t*)&smw[1][nB][k0 + kc];
        const uint32_t bl01 = *(const uint32_t*)&smw[1][nB][k0 + 8 + kc];
        const uint32_t bl10 = *(const uint32_t*)&smw[1][8 + nB][k0 + kc];
        const uint32_t bl11 = *(const uint32_t*)&smw[1][8 + nB][k0 + 8 + kc];

        mma16816(acc0, ah, bh00, bh01);
        mma16816(acc1, ah, bh10, bh11);
        mma16816(acc0, ah, bl00, bl01);
        mma16816(acc1, ah, bl10, bl11);
        mma16816(acc0, al, bh00, bh01);
        mma16816(acc1, al, bh10, bh11);
    }

    float* __restrict__ gs = g_scores + ((size_t)b * NNODE) * NJ;
    const int crow0 = row0 + (lane >> 2);
    const int crow1 = crow0 + 8;
    const int ccol  = (lane & 3) * 2;
    *(float2*)&gs[(size_t)crow0 * NJ + ccol]     = make_float2(acc0[0], acc0[1]);
    *(float2*)&gs[(size_t)crow1 * NJ + ccol]     = make_float2(acc0[2], acc0[3]);
    *(float2*)&gs[(size_t)crow0 * NJ + 8 + ccol] = make_float2(acc1[0], acc1[1]);
    *(float2*)&gs[(size_t)crow1 * NJ + 8 + ccol] = make_float2(acc1[2], acc1[3]);
}

// ---------------------------------------------------------------------------
// Gather + sigmoid, 4 edges per thread.  Also resets the build flags so the
// next replay of the captured graph sees a clean state (stream-ordered).
// ---------------------------------------------------------------------------
__device__ __forceinline__ float edge_score(int hidx, int tidx) {
    const float s = g_scores[(size_t)(hidx >> 3) * NJ + (hidx & 7)] +
                    g_scores[(size_t)(tidx >> 3) * NJ + 8 + (tidx & 7)];
    return 1.0f / (1.0f + __expf(-s));
}

__global__ void gather_kernel(const int4* __restrict__ head4,
                              const int4* __restrict__ tail4,
                              float4* __restrict__ out4, int total4) {
    const int i = blockIdx.x * blockDim.x + threadIdx.x;
    if (i == 0) { g_wdone = 0; g_wflag = 0; }   // reset for next launch
    if (i >= total4) return;
    const int4 h = head4[i];
    const int4 t = tail4[i];
    float4 o;
    o.x = edge_score(h.x, t.x);
    o.y = edge_score(h.y, t.y);
    o.z = edge_score(h.z, t.z);
    o.w = edge_score(h.w, t.w);
    out4[i] = o;
}

// ---------------------------------------------------------------------------
extern "C" void kernel_launch(void* const* d_in, const int* in_sizes, int n_in,
                              void* d_out, int out_size) {
    const float* x    = nullptr;
    const float* W    = nullptr;
    const int*   head = nullptr;
    const int*   tail = nullptr;
    const float* ssrc = nullptr;
    const float* strg = nullptr;
    for (int i = 0; i < n_in; ++i) {
        const int sz = in_sizes[i];
        if (sz == BSZ * NNODE * FIN) {
            x = (const float*)d_in[i];
        } else if (sz == NH * ND * FIN) {
            W = (const float*)d_in[i];
        } else if (sz == BSZ * EDG) {
            if (!head) head = (const int*)d_in[i];
            else       tail = (const int*)d_in[i];
        } else if (sz == BSZ * NH * ND) {
            if (!ssrc) ssrc = (const float*)d_in[i];
            else       strg = (const float*)d_in[i];
        }
    }
    float* out = (float*)d_out;

    score_mma_kernel<<<NBLK, 256>>>(x, W, ssrc, strg);

    const int total4 = BSZ * EDG / 4;
    gather_kernel<<<(total4 + 255) / 256, 256>>>(
        (const int4*)head, (const int4*)tail, (float4*)out, total4);
}